// round 3
// baseline (speedup 1.0000x reference)
#include <cuda_runtime.h>

// Problem dims
#define NNODES 207
#define LT     12
#define CIN    32
#define COUT   32
#define BATCH  256
#define NPAIR  (BATCH*COUT)        // 8192 (n,o) pairs
#define COLSF  (NNODES*LT)         // 2484 floats per (n,c) slice
#define PCOLS  (COLSF/2)           // 1242 float2 per slice
#define XELEMS (BATCH*CIN*COLSF)   // 20,348,928
#define NSQ    (NNODES*NNODES)

typedef unsigned long long u64;

// Scratch (static device globals — no allocation).
// g_mats: [0]=A (row-normalized), [1]=A2, [2]=M
__device__ float g_mats[3*NSQ];
__device__ float g_Y[XELEMS];      // channel-mixed intermediate, layout [n][o][w][l]

// ---- packed fp32x2 helpers (sm_100+ PTX) -------------------------------
__device__ __forceinline__ u64 pack2(float x) {
    u64 r; asm("mov.b64 %0, {%1, %1};" : "=l"(r) : "f"(x)); return r;
}
__device__ __forceinline__ void ffma2(u64 &d, u64 a, u64 b) {
    asm("fma.rn.f32x2 %0, %1, %2, %0;" : "+l"(d) : "l"(a), "l"(b));
}
__device__ __forceinline__ u64 add2(u64 a, u64 b) {
    u64 r; asm("add.rn.f32x2 %0, %1, %2;" : "=l"(r) : "l"(a), "l"(b)); return r;
}

// ---- K0a: row-normalized A = (adj + I) / rowsum ------------------------
__global__ void k_norm(const float* __restrict__ adj) {
    int v = blockIdx.x;
    __shared__ float red[256];
    float s = 0.f;
    for (int w = threadIdx.x; w < NNODES; w += 256)
        s += adj[v*NNODES + w] + (w == v ? 1.f : 0.f);
    red[threadIdx.x] = s;
    __syncthreads();
    for (int st = 128; st > 0; st >>= 1) {
        if (threadIdx.x < st) red[threadIdx.x] += red[threadIdx.x + st];
        __syncthreads();
    }
    float inv = 1.f / red[0];
    for (int w = threadIdx.x; w < NNODES; w += 256)
        g_mats[v*NNODES + w] = (adj[v*NNODES + w] + (w == v ? 1.f : 0.f)) * inv;
}

// ---- K0b: A2 = A @ A ---------------------------------------------------
__global__ void k_A2() {
    int v = blockIdx.x, u = threadIdx.x;
    if (u >= NNODES) return;
    const float* A = g_mats;
    float acc = 0.f;
    for (int w = 0; w < NNODES; w++)
        acc += A[v*NNODES + w] * A[w*NNODES + u];
    g_mats[NSQ + v*NNODES + u] = acc;
}

// ---- K0c: M = AL*I + c1*A + c2*A2 + c3*(A2@A) --------------------------
__global__ void k_M() {
    const float AL = 0.05f, BE = 0.95f;
    const float c1 = AL*BE, c2 = AL*BE*BE, c3 = BE*BE*BE;
    int v = blockIdx.x, u = threadIdx.x;
    if (u >= NNODES) return;
    const float* A  = g_mats;
    const float* A2 = g_mats + NSQ;
    float acc = 0.f;
    for (int w = 0; w < NNODES; w++)
        acc += A2[v*NNODES + w] * A[w*NNODES + u];
    float r = c3*acc + c2*A2[v*NNODES + u] + c1*A[v*NNODES + u]
            + (u == v ? AL : 0.f);
    g_mats[2*NSQ + v*NNODES + u] = r;
}

// ---- K1: channel mix  Y[n,o,w,l] = sum_c W[o,c] x[n,c,w,l] -------------
#define K1C 128   // float2 columns per block
__global__ __launch_bounds__(128) void k_cmix(const float* __restrict__ x,
                                              const float* __restrict__ W) {
    __shared__ u64 Xs [CIN][K1C];
    __shared__ u64 Ws2[CIN][COUT];   // [c][o], value duplicated into both halves
    int n    = blockIdx.y;
    int col0 = blockIdx.x * K1C;
    int t    = threadIdx.x;

    for (int i = t; i < CIN*COUT; i += 128) {
        int o = i >> 5, c = i & 31;
        Ws2[c][o] = pack2(W[i]);       // W layout (COUT, CIN): W[o*CIN+c]
    }
    const u64* x2 = (const u64*)x;
    int pc = col0 + t;
    bool valid = pc < PCOLS;
    for (int c = 0; c < CIN; c++)
        Xs[c][t] = valid ? x2[(size_t)n*CIN*PCOLS + (size_t)c*PCOLS + pc] : 0ull;
    __syncthreads();
    if (!valid) return;

    u64 acc[COUT];
#pragma unroll
    for (int o = 0; o < COUT; o++) acc[o] = 0ull;
#pragma unroll
    for (int c = 0; c < CIN; c++) {
        u64 xv = Xs[c][t];
#pragma unroll
        for (int o = 0; o < COUT; o++) ffma2(acc[o], Ws2[c][o], xv);
    }
    u64* y2 = (u64*)g_Y;
#pragma unroll
    for (int o = 0; o < COUT; o++)
        y2[((size_t)n*COUT + o)*PCOLS + pc] = acc[o];
}

// ---- K2: node GEMM  out[n,o,v,l] = sum_w M[v,w] Y[n,o,w,l] + b[o] ------
#define VT 32    // v-rows per block
#define GP 16    // (n,o) pairs per block
#define KC 16    // k chunk
__global__ __launch_bounds__(256) void k_node(const float* __restrict__ b,
                                              float* __restrict__ out) {
    __shared__ u64 Ms2[VT][KC];        // M[v][w] duplicated (m,m)
    __shared__ u64 Ysh[KC][GP*6];      // [kk][p*6+pc]
    int v0 = blockIdx.x * VT;          // 7 tiles (224 >= 207)
    int pb = blockIdx.y * GP;
    int tid = threadIdx.x;
    int ty = tid >> 5, tx = tid & 31;  // ty: 4 v's, tx: 3 packed cols

    u64 acc[4][3];
#pragma unroll
    for (int j = 0; j < 4; j++)
#pragma unroll
        for (int i = 0; i < 3; i++) acc[j][i] = 0ull;

    const u64*  yg = (const u64*)g_Y;
    const float* M = g_mats + 2*NSQ;

    for (int w0 = 0; w0 < NNODES; w0 += KC) {
        // stage M tile (duplicated): 512 elems, 2 per thread
        {
            int vl = tid >> 3;
            int k2 = (tid & 7) * 2;
            int v  = v0 + vl;
#pragma unroll
            for (int j = 0; j < 2; j++) {
                int w = w0 + k2 + j;
                float m = (v < NNODES && w < NNODES) ? M[v*NNODES + w] : 0.f;
                Ms2[vl][k2 + j] = pack2(m);
            }
        }
        // stage Y chunk: GP pairs x (KC w x 12 l) = 1536 u64, 6 per thread
#pragma unroll
        for (int j = 0; j < 6; j++) {
            int i  = tid + 256*j;
            int p  = i / 96, q = i % 96;   // q = kk*6 + pc (contiguous per pair)
            int kk = q / 6,  pcz = q % 6;
            int w  = w0 + kk;
            Ysh[kk][p*6 + pcz] = (w < NNODES)
                ? yg[(size_t)(pb + p)*PCOLS + (size_t)w*6 + pcz] : 0ull;
        }
        __syncthreads();
#pragma unroll
        for (int kk = 0; kk < KC; kk++) {
            u64 m2[4];
#pragma unroll
            for (int j = 0; j < 4; j++) m2[j] = Ms2[ty*4 + j][kk];
#pragma unroll
            for (int i = 0; i < 3; i++) {
                u64 yv = Ysh[kk][tx + 32*i];
#pragma unroll
                for (int j = 0; j < 4; j++) ffma2(acc[j][i], m2[j], yv);
            }
        }
        __syncthreads();
    }

    // epilogue: add bias, store packed (v,l) runs
    u64* o2 = (u64*)out;
#pragma unroll
    for (int i = 0; i < 3; i++) {
        int pcol = tx + 32*i;
        int p = pcol / 6, pcz = pcol % 6;
        int pair = pb + p;
        u64 b2 = pack2(b[pair & 31]);
#pragma unroll
        for (int j = 0; j < 4; j++) {
            int v = v0 + ty*4 + j;
            if (v < NNODES)
                o2[(size_t)pair*PCOLS + (size_t)v*6 + pcz] = add2(acc[j][i], b2);
        }
    }
}

extern "C" void kernel_launch(void* const* d_in, const int* in_sizes, int n_in,
                              void* d_out, int out_size) {
    const float* x   = (const float*)d_in[0];
    const float* adj = (const float*)d_in[1];
    const float* W   = (const float*)d_in[2];
    const float* b   = (const float*)d_in[3];
    float* out = (float*)d_out;

    k_norm<<<NNODES, 256>>>(adj);
    k_A2 <<<NNODES, 224>>>();
    k_M  <<<NNODES, 224>>>();
    k_cmix<<<dim3((PCOLS + K1C - 1)/K1C, BATCH), 128>>>(x, W);
    k_node<<<dim3((NNODES + VT - 1)/VT, NPAIR/GP), 256>>>(b, out);
}

// round 4
// speedup vs baseline: 1.0210x; 1.0210x over previous
#include <cuda_runtime.h>

// Problem dims
#define NNODES 207
#define LT     12
#define CIN    32
#define COUT   32
#define BATCH  256
#define NPAIR  (BATCH*COUT)        // 8192 (n,o) pairs
#define COLSF  (NNODES*LT)         // 2484 floats per (n,c) slice
#define PCOLS  (COLSF/2)           // 1242 float2 per slice
#define XELEMS (BATCH*CIN*COLSF)   // 20,348,928
#define NSQ    (NNODES*NNODES)

typedef unsigned long long u64;

// Scratch (static device globals — no allocation).
__device__ float g_mats[3*NSQ];    // [0]=A, [1]=A2, [2]=M
__device__ float g_Y[XELEMS];      // channel-mixed intermediate, [n][o][w][l]

// ---- packed fp32x2 helpers ---------------------------------------------
__device__ __forceinline__ u64 pack2(float x) {
    u64 r; asm("mov.b64 %0, {%1, %1};" : "=l"(r) : "f"(x)); return r;
}
__device__ __forceinline__ void ffma2(u64 &d, u64 a, u64 b) {
    asm("fma.rn.f32x2 %0, %1, %2, %0;" : "+l"(d) : "l"(a), "l"(b));
}
__device__ __forceinline__ u64 add2(u64 a, u64 b) {
    u64 r; asm("add.rn.f32x2 %0, %1, %2;" : "=l"(r) : "l"(a), "l"(b)); return r;
}

// ---- K0a: row-normalized A = (adj + I) / rowsum ------------------------
__global__ void k_norm(const float* __restrict__ adj) {
    int v = blockIdx.x;
    __shared__ float red[256];
    float s = 0.f;
    for (int w = threadIdx.x; w < NNODES; w += 256)
        s += adj[v*NNODES + w] + (w == v ? 1.f : 0.f);
    red[threadIdx.x] = s;
    __syncthreads();
    for (int st = 128; st > 0; st >>= 1) {
        if (threadIdx.x < st) red[threadIdx.x] += red[threadIdx.x + st];
        __syncthreads();
    }
    float inv = 1.f / red[0];
    for (int w = threadIdx.x; w < NNODES; w += 256)
        g_mats[v*NNODES + w] = (adj[v*NNODES + w] + (w == v ? 1.f : 0.f)) * inv;
}

// ---- K0b: A2 = A @ A ---------------------------------------------------
__global__ void k_A2() {
    int v = blockIdx.x, u = threadIdx.x;
    if (u >= NNODES) return;
    const float* A = g_mats;
    float acc = 0.f;
    for (int w = 0; w < NNODES; w++)
        acc += A[v*NNODES + w] * A[w*NNODES + u];
    g_mats[NSQ + v*NNODES + u] = acc;
}

// ---- K0c: M = AL*I + c1*A + c2*A2 + c3*(A2@A) --------------------------
__global__ void k_M() {
    const float AL = 0.05f, BE = 0.95f;
    const float c1 = AL*BE, c2 = AL*BE*BE, c3 = BE*BE*BE;
    int v = blockIdx.x, u = threadIdx.x;
    if (u >= NNODES) return;
    const float* A  = g_mats;
    const float* A2 = g_mats + NSQ;
    float acc = 0.f;
    for (int w = 0; w < NNODES; w++)
        acc += A2[v*NNODES + w] * A[w*NNODES + u];
    float r = c3*acc + c2*A2[v*NNODES + u] + c1*A[v*NNODES + u]
            + (u == v ? AL : 0.f);
    g_mats[2*NSQ + v*NNODES + u] = r;
}

// ---- K1: channel mix  Y[n,o,w,l] = sum_c W[o,c] x[n,c,w,l] -------------
// No X smem tile (it had zero sharing); x streamed straight to registers.
__global__ __launch_bounds__(256) void k_cmix(const float* __restrict__ x,
                                              const float* __restrict__ W) {
    __shared__ u64 Ws2[CIN][COUT];   // [c][o], value duplicated in both halves
    int n  = blockIdx.y;
    int pc = blockIdx.x * 256 + threadIdx.x;

    for (int i = threadIdx.x; i < CIN*COUT; i += 256) {
        int o = i >> 5, c = i & 31;
        Ws2[c][o] = pack2(W[i]);       // W layout (COUT, CIN)
    }
    __syncthreads();
    if (pc >= PCOLS) return;

    const u64* xp = (const u64*)x + (size_t)n*CIN*PCOLS + pc;

    u64 acc[COUT];
#pragma unroll
    for (int o = 0; o < COUT; o++) acc[o] = 0ull;
#pragma unroll 8
    for (int c = 0; c < CIN; c++) {
        u64 xv = xp[(size_t)c * PCOLS];
#pragma unroll
        for (int o = 0; o < COUT; o++) ffma2(acc[o], Ws2[c][o], xv);
    }
    u64* y2 = (u64*)g_Y + (size_t)n*COUT*PCOLS + pc;
#pragma unroll
    for (int o = 0; o < COUT; o++)
        y2[(size_t)o * PCOLS] = acc[o];
}

// ---- K2: node GEMM  out[n,o,v,l] = sum_w M[v,w] Y[n,o,w,l] + b[o] ------
// Thread tile 7v x 6 packed cols: 42 FFMA2 per kk vs 13 LDS -> fma-bound.
#define VT 56    // v-rows per block (4 tiles cover 207)
#define GP 32    // (n,o) pairs per block  (cols = GP*6 = 192 u64)
#define KC 16    // k chunk
#define YPAD 194 // padded Ysh row (u64) to break staging bank conflicts
__global__ __launch_bounds__(256, 2) void k_node(const float* __restrict__ b,
                                                 float* __restrict__ out) {
    __shared__ u64 Ms2[VT][KC];        // M[v][w] duplicated (m,m)
    __shared__ u64 Ysh[KC][YPAD];      // [kk][p*6+pcz]
    int v0  = blockIdx.x * VT;
    int pb  = blockIdx.y * GP;
    int tid = threadIdx.x;
    int ty  = tid >> 5, tx = tid & 31;  // ty: 7 v's each, tx: 6 packed cols

    u64 acc[7][6];
#pragma unroll
    for (int j = 0; j < 7; j++)
#pragma unroll
        for (int i = 0; i < 6; i++) acc[j][i] = 0ull;

    const u64*  yg = (const u64*)g_Y;
    const float* M = g_mats + 2*NSQ;

    for (int w0 = 0; w0 < NNODES; w0 += KC) {
        // stage M tile (duplicated): VT*KC = 896 elems
        for (int i = tid; i < VT*KC; i += 256) {
            int vl = i >> 4, k = i & 15;
            int v = v0 + vl, w = w0 + k;
            float m = (v < NNODES && w < NNODES) ? M[v*NNODES + w] : 0.f;
            Ms2[vl][k] = pack2(m);
        }
        // stage Y chunk: GP pairs x (KC w x 6 pcz) = 3072 u64, 12 per thread.
        // Mapping keeps each warp's global reads contiguous (96 u64 per pair).
#pragma unroll
        for (int j = 0; j < 12; j++) {
            int i   = tid + 256*j;
            int p   = i / 96, r = i % 96;
            int kk  = r / 6,  pcz = r % 6;
            int w   = w0 + kk;
            Ysh[kk][p*6 + pcz] = (w < NNODES)
                ? yg[(size_t)(pb + p)*PCOLS + (size_t)w*6 + pcz] : 0ull;
        }
        __syncthreads();
#pragma unroll
        for (int kk = 0; kk < KC; kk++) {
            u64 yv[6];
#pragma unroll
            for (int i = 0; i < 6; i++) yv[i] = Ysh[kk][tx + 32*i];
#pragma unroll
            for (int j = 0; j < 7; j++) {
                u64 m2 = Ms2[ty*7 + j][kk];
#pragma unroll
                for (int i = 0; i < 6; i++) ffma2(acc[j][i], m2, yv[i]);
            }
        }
        __syncthreads();
    }

    // epilogue: add bias, store packed (v,l) runs
    u64* o2 = (u64*)out;
#pragma unroll
    for (int i = 0; i < 6; i++) {
        int pcol = tx + 32*i;
        int p = pcol / 6, pcz = pcol % 6;
        int pair = pb + p;
        u64 b2 = pack2(b[pair & 31]);
#pragma unroll
        for (int j = 0; j < 7; j++) {
            int v = v0 + ty*7 + j;
            if (v < NNODES)
                o2[(size_t)pair*PCOLS + (size_t)v*6 + pcz] = add2(acc[j][i], b2);
        }
    }
}

extern "C" void kernel_launch(void* const* d_in, const int* in_sizes, int n_in,
                              void* d_out, int out_size) {
    const float* x   = (const float*)d_in[0];
    const float* adj = (const float*)d_in[1];
    const float* W   = (const float*)d_in[2];
    const float* b   = (const float*)d_in[3];
    float* out = (float*)d_out;

    k_norm<<<NNODES, 256>>>(adj);
    k_A2 <<<NNODES, 224>>>();
    k_M  <<<NNODES, 224>>>();
    k_cmix<<<dim3((PCOLS + 255)/256, BATCH), 256>>>(x, W);
    k_node<<<dim3((NNODES + VT - 1)/VT, NPAIR/GP), 256>>>(b, out);
}